// round 14
// baseline (speedup 1.0000x reference)
#include <cuda_runtime.h>
#include <cstdint>

// ---------------- problem constants ----------------
#define TOTAL   340704u        // 16224 + 64896 + 259584 candidates
#define OFF1    16224u
#define OFF2    81120u
#define KSEL    512u
#define NBOX    1536
#define NWORD   24             // 1536/64 mask words per row
#define BINBASE 0xBF199u       // (bits(0.6)|sign)>>12 ; keys for obj in (0.6,1]
#define NBIN    1640u          // 0xBF800 - 0xBF199 + 1
#define NBINP   1664u          // padded
#define POOLCAP 65536u
#define SORTCAP 4096
#define TRI_WORDS 19200        // sum_t 64*(24-t) upper-triangular u64 words
#define DYN_SMEM  (TRI_WORDS*8 + 48*32*4)   // tri + sdiag = 159744 B

typedef unsigned long long u64;
typedef uint32_t u32;

// ---------------- device scratch (static, allocation-free) ----------------
// Zero-initialized at module load; k_nms_out re-zeroes at the end of every
// run, so every execution starts from zeroed state (deterministic).
__device__ u32   g_hist[3*NBINP];
__device__ u32   g_validCount[3];
__device__ u32   g_selCount[3];
__device__ u32   g_poolCount[3];
__device__ u64   g_sel[3*512];
__device__ u64   g_pool[3*POOLCAP];
__device__ u64   g_sorted[NBOX];
__device__ float g_boxes[NBOX*9];
__device__ float g_nmsb[NBOX*5];     // x1,y1,x2,y2,area
__device__ int   g_valid[NBOX];
__device__ u64   g_mask[NBOX*NWORD];
__device__ u64   g_rowNZ[NWORD];     // bit j of word c: row c*64+j has any nonzero word
__device__ u64   g_diagNZ;           // bit c32: 32x32 diagonal block of chunk c32 nonzero

// ---------------- shared address/key computation ----------------
__device__ __forceinline__ void cand_addr(u32 i,
        const float* __restrict__ o13, const float* __restrict__ o26,
        const float* __restrict__ o52,
        float& x, int& s, u32& orig) {
    if (i < OFF1) {                 // H=13, HW=169, NHW=5408
        u32 loc = i;
        u32 a = loc / 5408u, r = loc - a*5408u;
        u32 n = r / 169u,  hw = r - n*169u;
        x = o13[(n*255u + a*85u)*169u + hw]; s = 0; orig = r*3u + a;
    } else if (i < OFF2) {          // H=26, HW=676, NHW=21632
        u32 loc = i - OFF1;
        u32 a = loc / 21632u, r = loc - a*21632u;
        u32 n = r / 676u,  hw = r - n*676u;
        x = o26[(n*255u + a*85u)*676u + hw]; s = 1; orig = r*3u + a;
    } else {                        // H=52, HW=2704, NHW=86528
        u32 loc = i - OFF2;
        u32 a = loc / 86528u, r = loc - a*86528u;
        u32 n = r / 2704u, hw = r - n*2704u;
        x = o52[(n*255u + a*85u)*2704u + hw]; s = 2; orig = r*3u + a;
    }
}

// ---------------- K1: 1640-bin histogram of score keys ----------------
__global__ __launch_bounds__(256) void k_hist(const float* __restrict__ o13,
                                              const float* __restrict__ o26,
                                              const float* __restrict__ o52) {
    __shared__ u32 sh[3*NBINP];
    __shared__ u32 svc[3];
    for (u32 b = threadIdx.x; b < 3u*NBINP; b += 256u) sh[b] = 0u;
    if (threadIdx.x < 3u) svc[threadIdx.x] = 0u;
    __syncthreads();
    for (u32 i = blockIdx.x*256u + threadIdx.x; i < TOTAL; i += 65536u) {
        float x; int s; u32 orig;
        cand_addr(i, o13, o26, o52, x, s, orig);
        float obj = 1.f / (1.f + expf(-x));
        if (obj > 0.6f) {
            u32 key = __float_as_uint(obj) | 0x80000000u;
            atomicAdd(&sh[(u32)s*NBINP + ((key >> 12) - BINBASE)], 1u);
            atomicAdd(&svc[s], 1u);
        }
    }
    __syncthreads();
    for (u32 b = threadIdx.x; b < 3u*NBINP; b += 256u) {
        u32 v = sh[b];
        if (v) atomicAdd(&g_hist[b], v);
    }
    if (threadIdx.x < 3u && svc[threadIdx.x]) atomicAdd(&g_validCount[threadIdx.x], svc[threadIdx.x]);
}

// ---------------- K2: recompute keys; select / pool ----------------
__global__ __launch_bounds__(256) void k_select(const float* __restrict__ o13,
                                                const float* __restrict__ o26,
                                                const float* __restrict__ o52) {
    __shared__ u32 ss[256];
    __shared__ int shBin[3];
    const u32 t = threadIdx.x;
    for (int s = 0; s < 3; s++) {
        if (g_validCount[s] < KSEL) {
            if (t == 0) shBin[s] = -2;            // select every valid directly
        } else {
            u32 b0 = t * 7u;
            u32 part = 0u;
            #pragma unroll
            for (u32 k = 0; k < 7u; k++) {
                u32 b = b0 + k;
                if (b < NBIN) part += g_hist[(u32)s*NBINP + b];
            }
            ss[t] = part;
            __syncthreads();
            for (u32 off = 1; off < 256u; off <<= 1) {   // inclusive suffix scan
                u32 add = (t + off < 256u) ? ss[t + off] : 0u;
                __syncthreads();
                ss[t] += add;
                __syncthreads();
            }
            u32 S = ss[t];
            u32 Sn = (t < 255u) ? ss[t + 1] : 0u;
            if (S >= KSEL && Sn < KSEL) {
                u32 cum = Sn;
                for (int k = 6; k >= 0; k--) {
                    u32 b = b0 + (u32)k;
                    if (b < NBIN) {
                        u32 c = g_hist[(u32)s*NBINP + b];
                        cum += c;
                        if (cum >= KSEL) { shBin[s] = (int)b; break; }
                    }
                }
            }
        }
        __syncthreads();
    }
    const int b0 = shBin[0], b1 = shBin[1], b2 = shBin[2];
    for (u32 i = blockIdx.x*256u + t; i < TOTAL; i += 65536u) {
        float x; int s; u32 orig;
        cand_addr(i, o13, o26, o52, x, s, orig);
        float obj = 1.f / (1.f + expf(-x));
        if (!(obj > 0.6f)) continue;
        u32 key = __float_as_uint(obj) | 0x80000000u;
        int hidx = (int)((key >> 12) - BINBASE);
        int tb = (s == 0) ? b0 : (s == 1) ? b1 : b2;
        if (hidx > tb) {
            u32 pos = atomicAdd(&g_selCount[s], 1u);
            g_sel[(u32)s*512u + pos] = ((u64)key << 32) | orig;
        } else if (hidx == tb) {
            u32 pos = atomicAdd(&g_poolCount[s], 1u);
            if (pos < POOLCAP)
                g_pool[(u32)s*POOLCAP + pos] = ((u64)key << 32) | (u32)(~orig);
        }
    }
}

// ---------------- K3: threshold-bin top-off + global bitonic sort ----------------
__global__ __launch_bounds__(1024) void k_sortfix() {
    __shared__ u64 sm[SORTCAP];        // 32 KB, reused
    __shared__ u32 sTot[3];
    __shared__ u32 scnt, srank;
    const u32 t = threadIdx.x;
    for (int s = 0; s < 3; s++) {
        u32 direct = g_selCount[s];
        u32 valid  = g_validCount[s];
        u32 need   = (valid >= KSEL) ? (KSEL - direct) : 0u;
        if (t == 0) sTot[s] = direct + need;
        u32 n = g_poolCount[s]; if (n > POOLCAP) n = POOLCAP;
        if (need > 0u) {
            if (n <= (u32)SORTCAP) {
                u32 P = 2u; while (P < n) P <<= 1u;
                for (u32 i = t; i < P; i += 1024u)
                    sm[i] = (i < n) ? g_pool[(u32)s*POOLCAP + i] : 0ull;
                __syncthreads();
                for (u32 k = 2; k <= P; k <<= 1)
                    for (u32 j = k >> 1; j > 0; j >>= 1) {
                        for (u32 i = t; i < P; i += 1024u) {
                            u32 ixj = i ^ j;
                            if (ixj > i) {
                                bool desc = ((i & k) == 0u);
                                u64 x = sm[i], y = sm[ixj];
                                if (desc ? (x < y) : (x > y)) { sm[i] = y; sm[ixj] = x; }
                            }
                        }
                        __syncthreads();
                    }
                for (u32 j = t; j < need; j += 1024u) {
                    u64 v = sm[j];
                    g_sel[(u32)s*512u + direct + j] =
                        (v & 0xFFFFFFFF00000000ull) | (u32)(~(u32)v);
                }
            } else {
                // fallback: exact selection via 64-bit binary search (v unique)
                u64 lo = 1ull, hi = 0xFFFFFFFFFFFFFFFFull;
                while (lo < hi) {
                    u64 mid = lo + ((hi - lo + 1ull) >> 1);
                    if (t == 0) scnt = 0u;
                    __syncthreads();
                    u32 c = 0u;
                    for (u32 j = t; j < n; j += 1024u)
                        if (g_pool[(u32)s*POOLCAP + j] >= mid) c++;
                    if (c) atomicAdd(&scnt, c);
                    __syncthreads();
                    u32 total = scnt;
                    __syncthreads();
                    if (total >= need) lo = mid; else hi = mid - 1ull;
                }
                if (t == 0) srank = 0u;
                __syncthreads();
                for (u32 j = t; j < n; j += 1024u) {
                    u64 v = g_pool[(u32)s*POOLCAP + j];
                    if (v >= lo) {
                        u32 p = atomicAdd(&srank, 1u);
                        if (p < need)
                            g_sel[(u32)s*512u + direct + p] =
                                (v & 0xFFFFFFFF00000000ull) | (u32)(~(u32)v);
                    }
                }
            }
        }
        __syncthreads();
    }
    // ---- global sort: 2048-entry bitonic (score desc, concat-pos asc) ----
    const u32 offc[3] = {0u, OFF1, OFF2};
    for (u32 j = t; j < 2048u; j += 1024u) {
        u64 v = 0ull;
        if (j < (u32)NBOX) {
            u32 s = j >> 9, p = j & 511u;
            if (p < sTot[s]) {
                u64 e = g_sel[s*512u + p];
                u32 key  = (u32)(e >> 32);
                u32 gidx = offc[s] + (u32)e;
                v = ((u64)key << 32) | (u32)(~gidx);
            }
        }
        sm[j] = v;
    }
    __syncthreads();
    for (u32 k = 2; k <= 2048u; k <<= 1)
        for (u32 j = k >> 1; j > 0; j >>= 1) {
            for (u32 i = t; i < 2048u; i += 1024u) {
                u32 ixj = i ^ j;
                if (ixj > i) {
                    bool desc = ((i & k) == 0u);
                    u64 x = sm[i], y = sm[ixj];
                    if (desc ? (x < y) : (x > y)) { sm[i] = y; sm[ixj] = x; }
                }
            }
            __syncthreads();
        }
    for (u32 j = t; j < (u32)NBOX; j += 1024u) g_sorted[j] = sm[j];
}

// ---------------- K4: decode winners (one warp per box) ----------------
__global__ void k_decode(const float* __restrict__ o13, const float* __restrict__ o26,
                         const float* __restrict__ o52,
                         const float* __restrict__ a13, const float* __restrict__ a26,
                         const float* __restrict__ a52) {
    int r = (blockIdx.x * blockDim.x + threadIdx.x) >> 5;
    int lane = threadIdx.x & 31;
    if (r >= NBOX) return;
    u64 e = g_sorted[r];
    u32 key = (u32)(e >> 32);
    if (key == 0u) {
        if (lane == 0) {
            #pragma unroll
            for (int k = 0; k < 9; k++) g_boxes[r*9+k] = 0.f;
            #pragma unroll
            for (int k = 0; k < 5; k++) g_nmsb[r*5+k] = 0.f;
            g_valid[r] = 0;
        }
        return;
    }
    u32 gidx = ~(u32)e;
    const float* p; const float* anc; int H; float ts; u32 loc;
    if (gidx < OFF1)      { p=o13; anc=a13; H=13; ts=32.f; loc=gidx; }
    else if (gidx < OFF2) { p=o26; anc=a26; H=26; ts=16.f; loc=gidx-OFF1; }
    else                  { p=o52; anc=a52; H=52; ts=8.f;  loc=gidx-OFF2; }
    u32 a = loc % 3u; u32 q = loc / 3u;
    u32 w = q % (u32)H; q /= (u32)H;
    u32 h = q % (u32)H; u32 n = q / (u32)H;
    int HW = H*H;
    const float* base = p + (size_t)(n*255u + a*85u)*HW + h*H + w;
    float aux = 0.f;
    if (lane >= 1 && lane <= 4) aux = base[lane * HW];
    float bv = -1e30f; int bc = 1 << 30;       // argmax 80 classes, first-max
    for (int c = lane; c < 80; c += 32) {
        float v = base[(5 + c) * HW];
        if (v > bv) { bv = v; bc = c; }
    }
    #pragma unroll
    for (int off = 16; off; off >>= 1) {
        float ov = __shfl_down_sync(0xffffffffu, bv, off);
        int   oc = __shfl_down_sync(0xffffffffu, bc, off);
        if (ov > bv || (ov == bv && oc < bc)) { bv = ov; bc = oc; }
    }
    float v1 = __shfl_sync(0xffffffffu, aux, 1);
    float v2 = __shfl_sync(0xffffffffu, aux, 2);
    float v3 = __shfl_sync(0xffffffffu, aux, 3);
    float v4 = __shfl_sync(0xffffffffu, aux, 4);
    if (lane == 0) {
        float obj = __uint_as_float(key ^ 0x80000000u);
        float cx = ((float)w + v1) * ts / 416.0f;
        float cy = ((float)h + v2) * ts / 416.0f;
        float bw = anc[a*2+0] * expf(v3) / 416.0f;
        float bh = anc[a*2+1] * expf(v4) / 416.0f;
        float* B = &g_boxes[r*9];
        B[0]=(float)n; B[1]=cx; B[2]=cy; B[3]=bw; B[4]=bh;
        B[5]=obj; B[6]=(float)bc; B[7]=(float)h; B[8]=(float)w;
        float x1 = cx - bw*0.5f, y1 = cy - bh*0.5f;
        float x2 = cx + bw*0.5f, y2 = cy + bh*0.5f;
        float area = fmaxf(x2-x1, 0.f) * fmaxf(y2-y1, 0.f);
        float* Nn = &g_nmsb[r*5];
        Nn[0]=x1; Nn[1]=y1; Nn[2]=x2; Nn[3]=y2; Nn[4]=area;
        g_valid[r] = 1;
    }
}

// ---------------- K5: suppression bitmask + NZ summary flags ----------------
__global__ void k_mask() {
    int cb = blockIdx.x, rb = blockIdx.y;
    __shared__ float c0[64], c1[64], c2[64], c3[64], ca[64];
    int t = threadIdx.x;
    int c = cb*64 + t;
    c0[t]=g_nmsb[c*5+0]; c1[t]=g_nmsb[c*5+1]; c2[t]=g_nmsb[c*5+2];
    c3[t]=g_nmsb[c*5+3]; ca[t]=g_nmsb[c*5+4];
    __syncthreads();
    int r = rb*64 + t;
    float x1=g_nmsb[r*5+0], y1=g_nmsb[r*5+1], x2=g_nmsb[r*5+2],
          y2=g_nmsb[r*5+3], ar=g_nmsb[r*5+4];
    u64 bits = 0ull;
    #pragma unroll 4
    for (int j = 0; j < 64; j++) {
        int cc = cb*64 + j;
        if (cc > r) {
            float ix = fmaxf(fminf(x2, c2[j]) - fmaxf(x1, c0[j]), 0.f);
            float iy = fmaxf(fminf(y2, c3[j]) - fmaxf(y1, c1[j]), 0.f);
            float iou = (ix * iy) / fmaxf(fminf(ar, ca[j]), 1e-9f);
            if (iou > 0.7f) bits |= (1ull << j);
        }
    }
    g_mask[r*NWORD + cb] = bits;
    // ---- warp-aggregated nonzero summaries (1-2 atomics per warp) ----
    int lane = t & 31, wid = t >> 5;
    u32 bal = __ballot_sync(0xffffffffu, bits != 0ull);
    if (lane == 0 && bal)
        atomicOr(&g_rowNZ[rb], (u64)bal << (wid*32));
    if (cb == rb) {
        u32 diagbits = (u32)(bits >> (wid*32));
        u32 dbal = __ballot_sync(0xffffffffu, diagbits != 0u);
        if (lane == 0 && dbal)
            atomicOr(&g_diagNZ, 1ull << (rb*2 + wid));
    }
}

// ---------------- K6: greedy scan — smem-resident triangular closure ----------------
// The upper-triangular mask (19200 u64 = 153.6 KB) plus a contiguous 32x32
// diagonal-block array (6 KB) are bulk-loaded into dynamic smem ONCE; the
// entire 48-sub-chunk greedy closure then runs inside warp 0 with no global
// traffic and no block barriers. Diagonal loads are asm-pinned (static
// offsets); folds are per-lane smem reads over kept rows only.
#define R8X(M,a,b,c2,d,e,f,g,h) M(a) M(b) M(c2) M(d) M(e) M(f) M(g) M(h)
#define SDECL(j) u32 d##j;
#define SLOAD(j) asm volatile("ld.shared.u32 %0, [%1];" \
                     : "=r"(d##j) : "r"(tb0 + (j)*4));
#define SSTEP(j) { u32 m_ = (u32)(((int)(av << (31-(j)))) >> 31); \
                   kp |= av & (1u<<(j)); \
                   av &= ~(d##j & m_); }

extern __shared__ u64 s_dyn[];   // [0,19200): tri ; then 48*32 u32 sdiag

__global__ __launch_bounds__(256, 1) void k_nms_out(float* __restrict__ out) {
    __shared__ u32 svalid32[48];
    __shared__ u32 skeep32[48];
    __shared__ u64 srowNZ[NWORD];
    u64* tri   = s_dyn;
    u32* sdiag = (u32*)(s_dyn + TRI_WORDS);
    const int tid  = threadIdx.x;
    const int lane = tid & 31;

    // ---- bulk load: triangular mask ----
    for (int t = 0; t < NWORD; t++) {
        const int W = NWORD - t;
        const int base = 64*(24*t - ((t*(t-1))>>1));
        const int n = 64*W;
        for (int idx = tid; idx < n; idx += 256) {
            int j = idx / W, k = idx - j*W;
            tri[base + idx] = g_mask[(size_t)(64*t + j)*NWORD + t + k];
        }
    }
    // ---- diagonal 32x32 blocks (contiguous, static-stride for asm loads) ----
    for (int i = tid; i < 48*32; i += 256) {
        int c32 = i >> 5, j = i & 31;
        int t = c32 >> 1;
        sdiag[i] = (u32)(g_mask[(size_t)(c32*32 + j)*NWORD + t] >> ((c32 & 1)*32));
    }
    if (tid < 48) {
        u32 v = 0u;
        for (int j = 0; j < 32; j++) if (g_valid[tid*32 + j]) v |= 1u << j;
        svalid32[tid] = v;
    }
    if (tid >= 64 && tid < 64 + NWORD) srowNZ[tid - 64] = g_rowNZ[tid - 64];
    __syncthreads();

    // ---- closure: entirely in warp 0, zero block syncs ----
    if (tid < 32) {
        const u64 diagNZ = g_diagNZ;
        u64 remv = 0ull;                    // lane w (w<NWORD) holds remv word w
        const u32 sdiag_base = (u32)__cvta_generic_to_shared(sdiag);
        for (int c32 = 0; c32 < 48; c32++) {
            const int t = c32 >> 1, half = c32 & 1, W = NWORD - t;
            const int triBase = 64*(24*t - ((t*(t-1))>>1));
            u64 rw = __shfl_sync(0xffffffffu, remv, t);
            u32 cur = (u32)(rw >> (half*32));
            u32 av0 = svalid32[c32] & ~cur;
            u32 kp;
            if (!((diagNZ >> c32) & 1ull)) {
                kp = av0;                   // diagonal block zero: keep all avail
            } else {
                kp = 0u;
                if (lane == 0) {
                    u32 av = av0;
                    u32 tb0 = sdiag_base + (u32)c32*128u;
                    R8X(SDECL, 0, 1, 2, 3, 4, 5, 6, 7)
                    R8X(SDECL, 8, 9,10,11,12,13,14,15)
                    R8X(SDECL,16,17,18,19,20,21,22,23)
                    R8X(SDECL,24,25,26,27,28,29,30,31)
                    R8X(SLOAD, 0, 1, 2, 3, 4, 5, 6, 7)
                    R8X(SLOAD, 8, 9,10,11,12,13,14,15)
                    R8X(SLOAD,16,17,18,19,20,21,22,23)
                    R8X(SLOAD,24,25,26,27,28,29,30,31)
                    do {
                        R8X(SSTEP, 0, 1, 2, 3, 4, 5, 6, 7)
                        if (!av) break;
                        R8X(SSTEP, 8, 9,10,11,12,13,14,15)
                        if (!av) break;
                        R8X(SSTEP,16,17,18,19,20,21,22,23)
                        if (!av) break;
                        R8X(SSTEP,24,25,26,27,28,29,30,31)
                    } while (0);
                }
                kp = __shfl_sync(0xffffffffu, kp, 0);
            }
            if (lane == 0) skeep32[c32] = kp;
            // fold: only kept rows that have any nonzero word (adaptive)
            u32 kb = kp & (u32)(srowNZ[t] >> (half*32));
            if (lane >= t && lane < NWORD && kb) {
                const u64* rowp = tri + triBase + (half*32)*W + (lane - t);
                u64 acc = 0ull;
                u32 it = kb;
                while (it) {
                    int j = __ffs(it) - 1;
                    it &= it - 1u;
                    acc |= rowp[j*W];
                }
                remv |= acc;
            }
        }
    }
    __syncthreads();

    // ---- masked output write ----
    for (int e = tid; e < NBOX*9; e += 256) {
        int r = e / 9;
        out[e] = g_boxes[e] * (((skeep32[r >> 5] >> (r & 31)) & 1u) ? 1.f : 0.f);
    }
    // ---- re-zero state for the next run ----
    for (u32 z = tid; z < 3u*NBINP; z += 256u) g_hist[z] = 0u;
    if (tid < 3) { g_validCount[tid] = 0u; g_selCount[tid] = 0u; g_poolCount[tid] = 0u; }
    if (tid < NWORD) g_rowNZ[tid] = 0ull;
    if (tid == 0) g_diagNZ = 0ull;
}

// ---------------- launcher: 6 graph nodes ----------------
extern "C" void kernel_launch(void* const* d_in, const int* in_sizes, int n_in,
                              void* d_out, int out_size) {
    const float* o13 = (const float*)d_in[0];
    const float* o26 = (const float*)d_in[1];
    const float* o52 = (const float*)d_in[2];
    const float* a13 = (const float*)d_in[3];
    const float* a26 = (const float*)d_in[4];
    const float* a52 = (const float*)d_in[5];
    float* out = (float*)d_out;

    // opt-in large dynamic smem for the NMS tail (idempotent, non-stream API)
    cudaFuncSetAttribute(k_nms_out, cudaFuncAttributeMaxDynamicSharedMemorySize,
                         DYN_SMEM);

    k_hist   <<<256, 256>>>(o13, o26, o52);
    k_select <<<256, 256>>>(o13, o26, o52);
    k_sortfix<<<1, 1024>>>();
    k_decode <<<192, 256>>>(o13, o26, o52, a13, a26, a52);
    k_mask   <<<dim3(24,24), 64>>>();
    k_nms_out<<<1, 256, DYN_SMEM>>>(out);
    (void)in_sizes; (void)n_in; (void)out_size;
}

// round 15
// speedup vs baseline: 1.2418x; 1.2418x over previous
#include <cuda_runtime.h>
#include <cstdint>

// ---------------- problem constants ----------------
#define TOTAL   340704u        // 16224 + 64896 + 259584 candidates
#define OFF1    16224u
#define OFF2    81120u
#define KSEL    512u
#define NBOX    1536
#define NWORD   24             // 1536/64 mask words per row
#define BINBASE 0xBF199u       // (bits(0.6)|sign)>>12 ; keys for obj in (0.6,1]
#define NBIN    1640u          // 0xBF800 - 0xBF199 + 1
#define NBINP   1664u          // padded
#define POOLCAP 65536u
#define SORTCAP 4096

typedef unsigned long long u64;
typedef uint32_t u32;

// ---------------- device scratch (static, allocation-free) ----------------
// Zero-initialized at module load; k_nms_out re-zeroes at the end of every
// run, so every execution starts from zeroed state (deterministic).
__device__ u32   g_hist[3*NBINP];
__device__ u32   g_validCount[3];
__device__ u32   g_selCount[3];
__device__ u32   g_poolCount[3];
__device__ u64   g_sel[3*512];
__device__ u64   g_pool[3*POOLCAP];
__device__ u64   g_sorted[NBOX];
__device__ float g_boxes[NBOX*9];
__device__ float g_nmsb[NBOX*5];     // x1,y1,x2,y2,area
__device__ int   g_valid[NBOX];
__device__ u64   g_maskT[NBOX*NWORD]; // TRANSPOSED: [col i][row-word w], bit j: row w*64+j<i suppresses i

// ---------------- shared address/key computation ----------------
__device__ __forceinline__ void cand_addr(u32 i,
        const float* __restrict__ o13, const float* __restrict__ o26,
        const float* __restrict__ o52,
        float& x, int& s, u32& orig) {
    if (i < OFF1) {                 // H=13, HW=169, NHW=5408
        u32 loc = i;
        u32 a = loc / 5408u, r = loc - a*5408u;
        u32 n = r / 169u,  hw = r - n*169u;
        x = o13[(n*255u + a*85u)*169u + hw]; s = 0; orig = r*3u + a;
    } else if (i < OFF2) {          // H=26, HW=676, NHW=21632
        u32 loc = i - OFF1;
        u32 a = loc / 21632u, r = loc - a*21632u;
        u32 n = r / 676u,  hw = r - n*676u;
        x = o26[(n*255u + a*85u)*676u + hw]; s = 1; orig = r*3u + a;
    } else {                        // H=52, HW=2704, NHW=86528
        u32 loc = i - OFF2;
        u32 a = loc / 86528u, r = loc - a*86528u;
        u32 n = r / 2704u, hw = r - n*2704u;
        x = o52[(n*255u + a*85u)*2704u + hw]; s = 2; orig = r*3u + a;
    }
}

// ---------------- K1: 1640-bin histogram of score keys ----------------
__global__ __launch_bounds__(256) void k_hist(const float* __restrict__ o13,
                                              const float* __restrict__ o26,
                                              const float* __restrict__ o52) {
    __shared__ u32 sh[3*NBINP];
    __shared__ u32 svc[3];
    for (u32 b = threadIdx.x; b < 3u*NBINP; b += 256u) sh[b] = 0u;
    if (threadIdx.x < 3u) svc[threadIdx.x] = 0u;
    __syncthreads();
    for (u32 i = blockIdx.x*256u + threadIdx.x; i < TOTAL; i += 65536u) {
        float x; int s; u32 orig;
        cand_addr(i, o13, o26, o52, x, s, orig);
        float obj = 1.f / (1.f + expf(-x));
        if (obj > 0.6f) {
            u32 key = __float_as_uint(obj) | 0x80000000u;
            atomicAdd(&sh[(u32)s*NBINP + ((key >> 12) - BINBASE)], 1u);
            atomicAdd(&svc[s], 1u);
        }
    }
    __syncthreads();
    for (u32 b = threadIdx.x; b < 3u*NBINP; b += 256u) {
        u32 v = sh[b];
        if (v) atomicAdd(&g_hist[b], v);
    }
    if (threadIdx.x < 3u && svc[threadIdx.x]) atomicAdd(&g_validCount[threadIdx.x], svc[threadIdx.x]);
}

// ---------------- K2: recompute keys; select / pool ----------------
__global__ __launch_bounds__(256) void k_select(const float* __restrict__ o13,
                                                const float* __restrict__ o26,
                                                const float* __restrict__ o52) {
    __shared__ u32 ss[256];
    __shared__ int shBin[3];
    const u32 t = threadIdx.x;
    for (int s = 0; s < 3; s++) {
        if (g_validCount[s] < KSEL) {
            if (t == 0) shBin[s] = -2;            // select every valid directly
        } else {
            u32 b0 = t * 7u;
            u32 part = 0u;
            #pragma unroll
            for (u32 k = 0; k < 7u; k++) {
                u32 b = b0 + k;
                if (b < NBIN) part += g_hist[(u32)s*NBINP + b];
            }
            ss[t] = part;
            __syncthreads();
            for (u32 off = 1; off < 256u; off <<= 1) {   // inclusive suffix scan
                u32 add = (t + off < 256u) ? ss[t + off] : 0u;
                __syncthreads();
                ss[t] += add;
                __syncthreads();
            }
            u32 S = ss[t];
            u32 Sn = (t < 255u) ? ss[t + 1] : 0u;
            if (S >= KSEL && Sn < KSEL) {
                u32 cum = Sn;
                for (int k = 6; k >= 0; k--) {
                    u32 b = b0 + (u32)k;
                    if (b < NBIN) {
                        u32 c = g_hist[(u32)s*NBINP + b];
                        cum += c;
                        if (cum >= KSEL) { shBin[s] = (int)b; break; }
                    }
                }
            }
        }
        __syncthreads();
    }
    const int b0 = shBin[0], b1 = shBin[1], b2 = shBin[2];
    for (u32 i = blockIdx.x*256u + t; i < TOTAL; i += 65536u) {
        float x; int s; u32 orig;
        cand_addr(i, o13, o26, o52, x, s, orig);
        float obj = 1.f / (1.f + expf(-x));
        if (!(obj > 0.6f)) continue;
        u32 key = __float_as_uint(obj) | 0x80000000u;
        int hidx = (int)((key >> 12) - BINBASE);
        int tb = (s == 0) ? b0 : (s == 1) ? b1 : b2;
        if (hidx > tb) {
            u32 pos = atomicAdd(&g_selCount[s], 1u);
            g_sel[(u32)s*512u + pos] = ((u64)key << 32) | orig;
        } else if (hidx == tb) {
            u32 pos = atomicAdd(&g_poolCount[s], 1u);
            if (pos < POOLCAP)
                g_pool[(u32)s*POOLCAP + pos] = ((u64)key << 32) | (u32)(~orig);
        }
    }
}

// ---------------- K3: threshold-bin top-off + global bitonic sort ----------------
__global__ __launch_bounds__(1024) void k_sortfix() {
    __shared__ u64 sm[SORTCAP];        // 32 KB, reused
    __shared__ u32 sTot[3];
    __shared__ u32 scnt, srank;
    const u32 t = threadIdx.x;
    for (int s = 0; s < 3; s++) {
        u32 direct = g_selCount[s];
        u32 valid  = g_validCount[s];
        u32 need   = (valid >= KSEL) ? (KSEL - direct) : 0u;
        if (t == 0) sTot[s] = direct + need;
        u32 n = g_poolCount[s]; if (n > POOLCAP) n = POOLCAP;
        if (need > 0u) {
            if (n <= (u32)SORTCAP) {
                u32 P = 2u; while (P < n) P <<= 1u;
                for (u32 i = t; i < P; i += 1024u)
                    sm[i] = (i < n) ? g_pool[(u32)s*POOLCAP + i] : 0ull;
                __syncthreads();
                for (u32 k = 2; k <= P; k <<= 1)
                    for (u32 j = k >> 1; j > 0; j >>= 1) {
                        for (u32 i = t; i < P; i += 1024u) {
                            u32 ixj = i ^ j;
                            if (ixj > i) {
                                bool desc = ((i & k) == 0u);
                                u64 x = sm[i], y = sm[ixj];
                                if (desc ? (x < y) : (x > y)) { sm[i] = y; sm[ixj] = x; }
                            }
                        }
                        __syncthreads();
                    }
                for (u32 j = t; j < need; j += 1024u) {
                    u64 v = sm[j];
                    g_sel[(u32)s*512u + direct + j] =
                        (v & 0xFFFFFFFF00000000ull) | (u32)(~(u32)v);
                }
            } else {
                // fallback: exact selection via 64-bit binary search (v unique)
                u64 lo = 1ull, hi = 0xFFFFFFFFFFFFFFFFull;
                while (lo < hi) {
                    u64 mid = lo + ((hi - lo + 1ull) >> 1);
                    if (t == 0) scnt = 0u;
                    __syncthreads();
                    u32 c = 0u;
                    for (u32 j = t; j < n; j += 1024u)
                        if (g_pool[(u32)s*POOLCAP + j] >= mid) c++;
                    if (c) atomicAdd(&scnt, c);
                    __syncthreads();
                    u32 total = scnt;
                    __syncthreads();
                    if (total >= need) lo = mid; else hi = mid - 1ull;
                }
                if (t == 0) srank = 0u;
                __syncthreads();
                for (u32 j = t; j < n; j += 1024u) {
                    u64 v = g_pool[(u32)s*POOLCAP + j];
                    if (v >= lo) {
                        u32 p = atomicAdd(&srank, 1u);
                        if (p < need)
                            g_sel[(u32)s*512u + direct + p] =
                                (v & 0xFFFFFFFF00000000ull) | (u32)(~(u32)v);
                    }
                }
            }
        }
        __syncthreads();
    }
    // ---- global sort: 2048-entry bitonic (score desc, concat-pos asc) ----
    const u32 offc[3] = {0u, OFF1, OFF2};
    for (u32 j = t; j < 2048u; j += 1024u) {
        u64 v = 0ull;
        if (j < (u32)NBOX) {
            u32 s = j >> 9, p = j & 511u;
            if (p < sTot[s]) {
                u64 e = g_sel[s*512u + p];
                u32 key  = (u32)(e >> 32);
                u32 gidx = offc[s] + (u32)e;
                v = ((u64)key << 32) | (u32)(~gidx);
            }
        }
        sm[j] = v;
    }
    __syncthreads();
    for (u32 k = 2; k <= 2048u; k <<= 1)
        for (u32 j = k >> 1; j > 0; j >>= 1) {
            for (u32 i = t; i < 2048u; i += 1024u) {
                u32 ixj = i ^ j;
                if (ixj > i) {
                    bool desc = ((i & k) == 0u);
                    u64 x = sm[i], y = sm[ixj];
                    if (desc ? (x < y) : (x > y)) { sm[i] = y; sm[ixj] = x; }
                }
            }
            __syncthreads();
        }
    for (u32 j = t; j < (u32)NBOX; j += 1024u) g_sorted[j] = sm[j];
}

// ---------------- K4: decode winners (one warp per box) ----------------
__global__ void k_decode(const float* __restrict__ o13, const float* __restrict__ o26,
                         const float* __restrict__ o52,
                         const float* __restrict__ a13, const float* __restrict__ a26,
                         const float* __restrict__ a52) {
    int r = (blockIdx.x * blockDim.x + threadIdx.x) >> 5;
    int lane = threadIdx.x & 31;
    if (r >= NBOX) return;
    u64 e = g_sorted[r];
    u32 key = (u32)(e >> 32);
    if (key == 0u) {
        if (lane == 0) {
            #pragma unroll
            for (int k = 0; k < 9; k++) g_boxes[r*9+k] = 0.f;
            #pragma unroll
            for (int k = 0; k < 5; k++) g_nmsb[r*5+k] = 0.f;
            g_valid[r] = 0;
        }
        return;
    }
    u32 gidx = ~(u32)e;
    const float* p; const float* anc; int H; float ts; u32 loc;
    if (gidx < OFF1)      { p=o13; anc=a13; H=13; ts=32.f; loc=gidx; }
    else if (gidx < OFF2) { p=o26; anc=a26; H=26; ts=16.f; loc=gidx-OFF1; }
    else                  { p=o52; anc=a52; H=52; ts=8.f;  loc=gidx-OFF2; }
    u32 a = loc % 3u; u32 q = loc / 3u;
    u32 w = q % (u32)H; q /= (u32)H;
    u32 h = q % (u32)H; u32 n = q / (u32)H;
    int HW = H*H;
    const float* base = p + (size_t)(n*255u + a*85u)*HW + h*H + w;
    float aux = 0.f;
    if (lane >= 1 && lane <= 4) aux = base[lane * HW];
    float bv = -1e30f; int bc = 1 << 30;       // argmax 80 classes, first-max
    for (int c = lane; c < 80; c += 32) {
        float v = base[(5 + c) * HW];
        if (v > bv) { bv = v; bc = c; }
    }
    #pragma unroll
    for (int off = 16; off; off >>= 1) {
        float ov = __shfl_down_sync(0xffffffffu, bv, off);
        int   oc = __shfl_down_sync(0xffffffffu, bc, off);
        if (ov > bv || (ov == bv && oc < bc)) { bv = ov; bc = oc; }
    }
    float v1 = __shfl_sync(0xffffffffu, aux, 1);
    float v2 = __shfl_sync(0xffffffffu, aux, 2);
    float v3 = __shfl_sync(0xffffffffu, aux, 3);
    float v4 = __shfl_sync(0xffffffffu, aux, 4);
    if (lane == 0) {
        float obj = __uint_as_float(key ^ 0x80000000u);
        float cx = ((float)w + v1) * ts / 416.0f;
        float cy = ((float)h + v2) * ts / 416.0f;
        float bw = anc[a*2+0] * expf(v3) / 416.0f;
        float bh = anc[a*2+1] * expf(v4) / 416.0f;
        float* B = &g_boxes[r*9];
        B[0]=(float)n; B[1]=cx; B[2]=cy; B[3]=bw; B[4]=bh;
        B[5]=obj; B[6]=(float)bc; B[7]=(float)h; B[8]=(float)w;
        float x1 = cx - bw*0.5f, y1 = cy - bh*0.5f;
        float x2 = cx + bw*0.5f, y2 = cy + bh*0.5f;
        float area = fmaxf(x2-x1, 0.f) * fmaxf(y2-y1, 0.f);
        float* Nn = &g_nmsb[r*5];
        Nn[0]=x1; Nn[1]=y1; Nn[2]=x2; Nn[3]=y2; Nn[4]=area;
        g_valid[r] = 1;
    }
}

// ---------------- K5: TRANSPOSED suppression bitmask ----------------
// g_maskT[c][rb] bit j = (row rb*64+j) < c  AND  iou(row, col c) > 0.7
// i.e. for box c, which lower-index boxes would suppress it if kept.
__global__ void k_maskT() {
    int rb = blockIdx.x, cb = blockIdx.y;   // row block (suppressors), col block
    __shared__ float r0[64], r1[64], r2[64], r3[64], ra[64];
    int t = threadIdx.x;
    int rr = rb*64 + t;
    r0[t]=g_nmsb[rr*5+0]; r1[t]=g_nmsb[rr*5+1]; r2[t]=g_nmsb[rr*5+2];
    r3[t]=g_nmsb[rr*5+3]; ra[t]=g_nmsb[rr*5+4];
    __syncthreads();
    int c = cb*64 + t;
    float x1=g_nmsb[c*5+0], y1=g_nmsb[c*5+1], x2=g_nmsb[c*5+2],
          y2=g_nmsb[c*5+3], ar=g_nmsb[c*5+4];
    u64 bits = 0ull;
    #pragma unroll 4
    for (int j = 0; j < 64; j++) {
        int rj = rb*64 + j;
        if (rj < c) {
            float ix = fmaxf(fminf(x2, r2[j]) - fmaxf(x1, r0[j]), 0.f);
            float iy = fmaxf(fminf(y2, r3[j]) - fmaxf(y1, r1[j]), 0.f);
            float iou = (ix * iy) / fmaxf(fminf(ar, ra[j]), 1e-9f);
            if (iou > 0.7f) bits |= (1ull << j);
        }
    }
    g_maskT[c*NWORD + rb] = bits;
}

// ---------------- K6: NMS via exact Jacobi fixpoint + output + re-zero ----------------
// k <- valid; iterate k <- T(k), T(k)[i] = valid[i] & !OR_{j<i}(k[j] & M[j][i]).
// Unique fixpoint = greedy NMS result; correct prefix grows >=1 box/iteration
// (terminates <= NBOX, typically a handful). Fully parallel per iteration.
__global__ __launch_bounds__(1024) void k_nms_out(float* __restrict__ out) {
    __shared__ u32 kw32[48];
    __shared__ u32 valid32[48];
    __shared__ u64 k64[NWORD];
    __shared__ int sChanged;
    const int tid  = threadIdx.x;
    const int lane = tid & 31;

    // build valid words via ballots (warp w handles boxes w*32..w*32+31)
    {
        int i = tid;                               // boxes 0..1023
        u32 b = __ballot_sync(0xffffffffu, g_valid[i] != 0);
        if (lane == 0) { valid32[tid >> 5] = b; kw32[tid >> 5] = b; }
        if (tid < 512) {
            int i2 = 1024 + tid;                   // boxes 1024..1535
            u32 b2 = __ballot_sync(0xffffffffu, g_valid[i2] != 0);
            if (lane == 0) { valid32[32 + (tid >> 5)] = b2; kw32[32 + (tid >> 5)] = b2; }
        }
    }
    __syncthreads();

    for (int it = 0; it < NBOX; it++) {
        if (tid < NWORD) k64[tid] = (u64)kw32[2*tid] | ((u64)kw32[2*tid+1] << 32);
        if (tid == 0) sChanged = 0;
        __syncthreads();
        // pass 0: boxes 0..1023 ; pass 1: boxes 1024..1535
        u32 nb0, nb1 = 0u;
        {
            int i = tid;
            u64 acc = 0ull;
            int wmax = i >> 6;
            const u64* mt = &g_maskT[(size_t)i * NWORD];
            for (int w = 0; w <= wmax; w++) acc |= mt[w] & k64[w];
            bool keep = ((valid32[i >> 5] >> (i & 31)) & 1u) && (acc == 0ull);
            nb0 = __ballot_sync(0xffffffffu, keep);
        }
        if (tid < 512) {
            int i = 1024 + tid;
            u64 acc = 0ull;
            int wmax = i >> 6;
            const u64* mt = &g_maskT[(size_t)i * NWORD];
            for (int w = 0; w <= wmax; w++) acc |= mt[w] & k64[w];
            bool keep = ((valid32[i >> 5] >> (i & 31)) & 1u) && (acc == 0ull);
            nb1 = __ballot_sync(0xffffffffu, keep);
        }
        if (lane == 0) {
            int w0 = tid >> 5;
            if (nb0 != kw32[w0]) { kw32[w0] = nb0; sChanged = 1; }
            if (tid < 512) {
                int w1 = 32 + (tid >> 5);
                if (nb1 != kw32[w1]) { kw32[w1] = nb1; sChanged = 1; }
            }
        }
        __syncthreads();
        if (!sChanged) break;
    }

    // ---- masked output write ----
    for (int e = tid; e < NBOX*9; e += 1024) {
        int r = e / 9;
        out[e] = g_boxes[e] * (((kw32[r >> 5] >> (r & 31)) & 1u) ? 1.f : 0.f);
    }
    // ---- re-zero selection state for the next run ----
    for (u32 z = tid; z < 3u*NBINP; z += 1024u) g_hist[z] = 0u;
    if (tid < 3) { g_validCount[tid] = 0u; g_selCount[tid] = 0u; g_poolCount[tid] = 0u; }
}

// ---------------- launcher: 6 graph nodes ----------------
extern "C" void kernel_launch(void* const* d_in, const int* in_sizes, int n_in,
                              void* d_out, int out_size) {
    const float* o13 = (const float*)d_in[0];
    const float* o26 = (const float*)d_in[1];
    const float* o52 = (const float*)d_in[2];
    const float* a13 = (const float*)d_in[3];
    const float* a26 = (const float*)d_in[4];
    const float* a52 = (const float*)d_in[5];
    float* out = (float*)d_out;

    k_hist   <<<256, 256>>>(o13, o26, o52);
    k_select <<<256, 256>>>(o13, o26, o52);
    k_sortfix<<<1, 1024>>>();
    k_decode <<<192, 256>>>(o13, o26, o52, a13, a26, a52);
    k_maskT  <<<dim3(24,24), 64>>>();
    k_nms_out<<<1, 1024>>>(out);
    (void)in_sizes; (void)n_in; (void)out_size;
}